// round 17
// baseline (speedup 1.0000x reference)
#include <cuda_runtime.h>
#include <cuda_bf16.h>
#include <cstdint>
#include <math.h>

// ---------------------------------------------------------------------------
// Problem constants: B=4, S=1024, D=768, H=12, hd=64, F=3072, L=6
// ---------------------------------------------------------------------------
#define T_TOK   4096
#define DIM     768
#define QKVDIM  2304
#define FFDIM   3072
#define NLAYER  6
#define NHEAD   12
#define HDIM    64
#define SEQ     1024

// -------------------- scratch buffers (no cudaMalloc allowed) ---------------
__device__ float g_h   [T_TOK * DIM];     // residual stream (fp32)
__device__ float g_qkv [T_TOK * QKVDIM];  // qkv (fp32, attention input)
__device__ float g_attn[T_TOK * DIM];     // attention output (fp32)
__device__ float g_tmp [T_TOK * DIM];     // Wo / FFN2 output (fp32)
__device__ float g_ffn [T_TOK * FFDIM];   // FFN hidden (fp32, post-ReLU)
__device__ float g_wt  [FFDIM * DIM * 4 / 3]; // transpose temp

// int8 activation slices + per-row scales
__device__ int8_t g_hA1  [T_TOK * DIM];
__device__ int8_t g_hA2  [T_TOK * DIM];
__device__ float  g_sah  [T_TOK];
__device__ int8_t g_atA1 [T_TOK * DIM];
__device__ int8_t g_atA2 [T_TOK * DIM];
__device__ float  g_saat [T_TOK];
__device__ int8_t g_ffA1 [T_TOK * FFDIM];
__device__ int8_t g_ffA2 [T_TOK * FFDIM];
__device__ float  g_saff [T_TOK];

// int8 weight slices ([N,K] layout) + per-output-row scales
__device__ int8_t g_Bq1[NLAYER * QKVDIM * DIM];
__device__ int8_t g_Bq2[NLAYER * QKVDIM * DIM];
__device__ float  g_sbq[NLAYER * QKVDIM];
__device__ int8_t g_Bo1[NLAYER * DIM * DIM];
__device__ int8_t g_Bo2[NLAYER * DIM * DIM];
__device__ float  g_sbo[NLAYER * DIM];
__device__ int8_t g_B11[NLAYER * FFDIM * DIM];
__device__ int8_t g_B12[NLAYER * FFDIM * DIM];
__device__ float  g_sb1[NLAYER * FFDIM];
__device__ int8_t g_B21[NLAYER * DIM * FFDIM];
__device__ int8_t g_B22[NLAYER * DIM * FFDIM];
__device__ float  g_sb2[NLAYER * DIM];

// -------------------- PTX helpers -------------------------------------------
__device__ __forceinline__ uint32_t s2u(const void* p) {
    uint32_t a;
    asm("{ .reg .u64 t; cvta.to.shared.u64 t, %1; cvt.u32.u64 %0, t; }"
        : "=r"(a) : "l"(p));
    return a;
}

#define CP_ASYNC16(dst, src) \
    asm volatile("cp.async.cg.shared.global [%0], [%1], 16;" \
                 :: "r"(dst), "l"(src) : "memory")
#define CP_COMMIT() asm volatile("cp.async.commit_group;" ::: "memory")
#define CP_WAIT0()  asm volatile("cp.async.wait_group 0;" ::: "memory")

__device__ __forceinline__ void ldsm4(uint32_t* r, uint32_t addr) {
    asm volatile("ldmatrix.sync.aligned.m8n8.x4.shared.b16 {%0,%1,%2,%3}, [%4];"
                 : "=r"(r[0]), "=r"(r[1]), "=r"(r[2]), "=r"(r[3]) : "r"(addr));
}

// m16n8k32 s8 mma: D(s32) += A(s8)*B(s8)
__device__ __forceinline__ void mma_s8(int* c, const uint32_t* a,
                                       uint32_t b0, uint32_t b1) {
    asm volatile(
        "mma.sync.aligned.m16n8k32.row.col.s32.s8.s8.s32 "
        "{%0,%1,%2,%3}, {%4,%5,%6,%7}, {%8,%9}, {%0,%1,%2,%3};"
        : "+r"(c[0]), "+r"(c[1]), "+r"(c[2]), "+r"(c[3])
        : "r"(a[0]), "r"(a[1]), "r"(a[2]), "r"(a[3]), "r"(b0), "r"(b1));
}

// quantize: v = sa*(q1 + q2/254), q1/q2 int8 (exact up to q2 rounding)
__device__ __forceinline__ void quant2(float v, float inv, int8_t& q1o, int8_t& q2o) {
    float q = v * inv;
    int q1 = __float2int_rn(q);
    int q2 = __float2int_rn((q - (float)q1) * 254.f);
    q1o = (int8_t)q1;
    q2o = (int8_t)q2;
}

// ---------------------------------------------------------------------------
// int8x3 tensor-core GEMM: C[M,N] = A[M,K] @ W[N,K]^T + bias, opt ReLU.
// A slices A1,A2 + row scales sa; W slices B1,B2 + row scales sb.
// CTA 128x64, 8 warps (4m x 2n), warp tile 32x32, K-tile 64 bytes,
// double-buffered cp.async, ldmatrix fragments (s8-k32 bytes == bf16-k16).
// ---------------------------------------------------------------------------
#define ISTR   80                      // bytes per padded smem row (64 data)
#define PA1 0
#define PA2 (128 * ISTR)               // 10240
#define PB1 (2 * 128 * ISTR)           // 20480
#define PB2 (PB1 + 64 * ISTR)          // 25600
#define ISTAGE (PB2 + 64 * ISTR)       // 30720
#define GEMM_SMEM_BYTES (2 * ISTAGE)   // 61440

__global__ __launch_bounds__(256, 2)
void gemm_i8(const int8_t* __restrict__ A1, const int8_t* __restrict__ A2,
             const float* __restrict__ sa,
             const int8_t* __restrict__ B1, const int8_t* __restrict__ B2,
             const float* __restrict__ sb,
             const float* __restrict__ bias, float* __restrict__ C,
             int M, int N, int K, int relu)
{
    extern __shared__ __align__(16) char smc[];
    const uint32_t sbm = s2u(smc);
    const int tid  = threadIdx.x;
    const int wid  = tid >> 5;
    const int lane = tid & 31;
    const int gr   = lane >> 2;
    const int tig  = lane & 3;
    const int bn = blockIdx.x;       // N/64
    const int bm = blockIdx.y;       // M/128

    const int m0w = (wid >> 1) * 32;
    const int n0w = (wid & 1) * 32;

    const int8_t* A1b = A1 + (size_t)bm * 128 * K;
    const int8_t* A2b = A2 + (size_t)bm * 128 * K;
    const int8_t* B1b = B1 + (size_t)bn * 64 * K;
    const int8_t* B2b = B2 + (size_t)bn * 64 * K;
    const int nk = K >> 6;

    // loader geometry
    const int arow = tid >> 2;
    const int aoffb = (tid & 3) * 16;
    const int brow = tid >> 2;
    const int boffb = (tid & 3) * 16;

    // ldmatrix per-lane offsets
    // A: bit3 -> +8 rows, bit4 -> +16 bytes (k-half)  => r0..r3 = a0..a3
    const uint32_t afrag = (uint32_t)(m0w + (lane & 7) + ((lane >> 3) & 1) * 8) * ISTR
                         + ((lane >> 4) & 1) * 16;
    // B: bit3 -> +16 bytes (k-half), bit4 -> +8 rows  => (r0,r1)=n-tile0, (r2,r3)=n-tile1
    const uint32_t bfrag = (uint32_t)(n0w + (lane & 7) + ((lane >> 4) & 1) * 8) * ISTR
                         + ((lane >> 3) & 1) * 16;

    // ---- preload tile 0 ----
    {
        uint32_t d;
        #pragma unroll
        for (int c = 0; c < 2; ++c) {
            int row = arow + c * 64;
            d = sbm + PA1 + (uint32_t)row * ISTR + aoffb;
            CP_ASYNC16(d, A1b + (size_t)row * K + aoffb);
            d = sbm + PA2 + (uint32_t)row * ISTR + aoffb;
            CP_ASYNC16(d, A2b + (size_t)row * K + aoffb);
        }
        d = sbm + PB1 + (uint32_t)brow * ISTR + boffb;
        CP_ASYNC16(d, B1b + (size_t)brow * K + boffb);
        d = sbm + PB2 + (uint32_t)brow * ISTR + boffb;
        CP_ASYNC16(d, B2b + (size_t)brow * K + boffb);
        CP_COMMIT();
    }
    CP_WAIT0();
    __syncthreads();

    int acc1[2][4][4], acc2[2][4][4];
    #pragma unroll
    for (int mt = 0; mt < 2; ++mt)
        #pragma unroll
        for (int nt = 0; nt < 4; ++nt)
            #pragma unroll
            for (int r = 0; r < 4; ++r) {
                acc1[mt][nt][r] = 0;
                acc2[mt][nt][r] = 0;
            }

    for (int kt = 0; kt < nk; ++kt) {
        const int s = kt & 1;
        const bool more = (kt + 1 < nk);

        if (more) {
            const int ko = (kt + 1) * 64;
            const uint32_t so = sbm + (s ^ 1) * ISTAGE;
            uint32_t d;
            #pragma unroll
            for (int c = 0; c < 2; ++c) {
                int row = arow + c * 64;
                d = so + PA1 + (uint32_t)row * ISTR + aoffb;
                CP_ASYNC16(d, A1b + (size_t)row * K + ko + aoffb);
                d = so + PA2 + (uint32_t)row * ISTR + aoffb;
                CP_ASYNC16(d, A2b + (size_t)row * K + ko + aoffb);
            }
            d = so + PB1 + (uint32_t)brow * ISTR + boffb;
            CP_ASYNC16(d, B1b + (size_t)brow * K + ko + boffb);
            d = so + PB2 + (uint32_t)brow * ISTR + boffb;
            CP_ASYNC16(d, B2b + (size_t)brow * K + ko + boffb);
            CP_COMMIT();
        }

        const uint32_t st = sbm + s * ISTAGE;
        #pragma unroll
        for (int kq = 0; kq < 2; ++kq) {
            // A fragments (slice1, slice2) for both m-tiles
            uint32_t a1f[2][4], a2f[2][4];
            #pragma unroll
            for (int mt = 0; mt < 2; ++mt) {
                uint32_t ad = st + afrag + mt * (16 * ISTR) + kq * 32;
                ldsm4(a1f[mt], ad + PA1);
                ldsm4(a2f[mt], ad + PA2);
            }
            // B fragments for 4 n-tiles
            uint32_t b1f[4][2], b2f[4][2];
            #pragma unroll
            for (int p = 0; p < 2; ++p) {
                uint32_t r[4];
                uint32_t bd = st + bfrag + p * (16 * ISTR) + kq * 32;
                ldsm4(r, bd + PB1);
                b1f[2 * p][0] = r[0]; b1f[2 * p][1] = r[1];
                b1f[2 * p + 1][0] = r[2]; b1f[2 * p + 1][1] = r[3];
                ldsm4(r, bd + PB2);
                b2f[2 * p][0] = r[0]; b2f[2 * p][1] = r[1];
                b2f[2 * p + 1][0] = r[2]; b2f[2 * p + 1][1] = r[3];
            }
            // pass 1: A1*B1 -> acc1
            #pragma unroll
            for (int mt = 0; mt < 2; ++mt)
                #pragma unroll
                for (int nt = 0; nt < 4; ++nt)
                    mma_s8(acc1[mt][nt], a1f[mt], b1f[nt][0], b1f[nt][1]);
            // pass 2: A1*B2 -> acc2
            #pragma unroll
            for (int mt = 0; mt < 2; ++mt)
                #pragma unroll
                for (int nt = 0; nt < 4; ++nt)
                    mma_s8(acc2[mt][nt], a1f[mt], b2f[nt][0], b2f[nt][1]);
            // pass 3: A2*B1 -> acc2
            #pragma unroll
            for (int mt = 0; mt < 2; ++mt)
                #pragma unroll
                for (int nt = 0; nt < 4; ++nt)
                    mma_s8(acc2[mt][nt], a2f[mt], b1f[nt][0], b1f[nt][1]);
        }

        if (more) {
            CP_WAIT0();
            __syncthreads();
        }
    }

    // ---- epilogue: C = sa*sb*(acc1 + acc2/254) + bias ----
    const float inv254 = 1.0f / 254.0f;
    #pragma unroll
    for (int nt = 0; nt < 4; ++nt) {
        const int gc = bn * 64 + n0w + nt * 8 + tig * 2;
        float2 bv  = *(const float2*)(bias + gc);
        float2 sbv = *(const float2*)(sb + gc);
        #pragma unroll
        for (int mt = 0; mt < 2; ++mt) {
            const int gm = bm * 128 + m0w + mt * 16 + gr;
            float sa0 = sa[gm];
            float sa1 = sa[gm + 8];
            float v0 = sa0 * sbv.x * ((float)acc1[mt][nt][0] + (float)acc2[mt][nt][0] * inv254) + bv.x;
            float v1 = sa0 * sbv.y * ((float)acc1[mt][nt][1] + (float)acc2[mt][nt][1] * inv254) + bv.y;
            float v2 = sa1 * sbv.x * ((float)acc1[mt][nt][2] + (float)acc2[mt][nt][2] * inv254) + bv.x;
            float v3 = sa1 * sbv.y * ((float)acc1[mt][nt][3] + (float)acc2[mt][nt][3] * inv254) + bv.y;
            if (relu) {
                v0 = fmaxf(v0, 0.f); v1 = fmaxf(v1, 0.f);
                v2 = fmaxf(v2, 0.f); v3 = fmaxf(v3, 0.f);
            }
            *(float2*)(C + (size_t)gm * N + gc) = make_float2(v0, v1);
            *(float2*)(C + (size_t)(gm + 8) * N + gc) = make_float2(v2, v3);
        }
    }
}

// ---------------------------------------------------------------------------
// Plain fp32 transpose: out[C,R] = in[R,C]^T
// ---------------------------------------------------------------------------
__global__ __launch_bounds__(256)
void transpose_f32(const float* __restrict__ in, float* __restrict__ out,
                   int R, int C)
{
    __shared__ float t[32][33];
    const int c0 = blockIdx.x * 32, r0 = blockIdx.y * 32;
    const int x = threadIdx.x, y = threadIdx.y;
    #pragma unroll
    for (int j = 0; j < 32; j += 8)
        t[y + j][x] = in[(size_t)(r0 + y + j) * C + c0 + x];
    __syncthreads();
    #pragma unroll
    for (int j = 0; j < 32; j += 8)
        out[(size_t)(c0 + y + j) * R + r0 + x] = t[x][y + j];
}

// ---------------------------------------------------------------------------
// Row quantize: one block per row of width W. Emits int8 slices + scale.
// ---------------------------------------------------------------------------
__device__ __forceinline__ float block_max256(float x, float* red)
{
    #pragma unroll
    for (int off = 16; off > 0; off >>= 1)
        x = fmaxf(x, __shfl_xor_sync(0xffffffffu, x, off));
    if ((threadIdx.x & 31) == 0) red[threadIdx.x >> 5] = x;
    __syncthreads();
    float r = fmaxf(fmaxf(fmaxf(red[0], red[1]), fmaxf(red[2], red[3])),
                    fmaxf(fmaxf(red[4], red[5]), fmaxf(red[6], red[7])));
    __syncthreads();
    return r;
}

__global__ __launch_bounds__(256)
void convert_rows(const float* __restrict__ in, int8_t* __restrict__ p1,
                  int8_t* __restrict__ p2, float* __restrict__ sc, int W)
{
    __shared__ float red[8];
    const int row = blockIdx.x;
    const int tid = threadIdx.x;
    const size_t base = (size_t)row * W;

    float mx = 0.f;
    for (int j = tid; j < W; j += 256)
        mx = fmaxf(mx, fabsf(in[base + j]));
    mx = block_max256(mx, red);
    mx = fmaxf(mx, 1e-30f);
    const float saV = mx / 127.f;
    const float inv = 127.f / mx;
    if (tid == 0) sc[row] = saV;

    for (int j = tid; j < W; j += 256) {
        int8_t q1, q2;
        quant2(in[base + j], inv, q1, q2);
        p1[base + j] = q1;
        p2[base + j] = q2;
    }
}

// -------------------- packed f32x2 helpers (attention) ----------------------
__device__ __forceinline__ unsigned long long pk2(float x) {
    unsigned long long r;
    asm("mov.b64 %0, {%1, %1};" : "=l"(r) : "f"(x));
    return r;
}
__device__ __forceinline__ void fma2(unsigned long long& c,
                                     unsigned long long a,
                                     unsigned long long b) {
    asm("fma.rn.f32x2 %0, %1, %2, %0;" : "+l"(c) : "l"(a), "l"(b));
}
__device__ __forceinline__ unsigned long long mul2(unsigned long long a,
                                                   unsigned long long b) {
    unsigned long long r;
    asm("mul.rn.f32x2 %0, %1, %2;" : "=l"(r) : "l"(a), "l"(b));
    return r;
}
__device__ __forceinline__ float2 up2(unsigned long long v) {
    float2 f;
    asm("mov.b64 {%0, %1}, %2;" : "=f"(f.x), "=f"(f.y) : "l"(v));
    return f;
}

// ---------------------------------------------------------------------------
// Flash-style attention (fp32 in/out, proven correct).
// ---------------------------------------------------------------------------
__global__ __launch_bounds__(256)
void attn_kernel(const float* __restrict__ qkv, float* __restrict__ out)
{
    __shared__ __align__(16) float qst[64 * 64];
    __shared__ __align__(16) float kp [64 * 64];
    __shared__ __align__(16) float vs [64 * 64];

    const int tid = threadIdx.x;
    const int tx = tid & 15;
    const int ty = tid >> 4;
    const int qt = blockIdx.x;
    const int hh = blockIdx.y;
    const int bb = blockIdx.z;

    const size_t tok0 = (size_t)bb * SEQ;
    const float* qb = qkv + (tok0 + qt * 64) * QKVDIM + hh * HDIM;

    #pragma unroll
    for (int p = 0; p < 4; ++p) {
        int f = tid + p * 256;
        int row = f >> 4;
        int c4 = (f & 15) << 2;
        float4 v = *(const float4*)(qb + (size_t)row * QKVDIM + c4);
        qst[(c4 + 0) * 64 + row] = v.x;
        qst[(c4 + 1) * 64 + row] = v.y;
        qst[(c4 + 2) * 64 + row] = v.z;
        qst[(c4 + 3) * 64 + row] = v.w;
    }

    float m[4], l[4];
    unsigned long long op[4][2];
    #pragma unroll
    for (int i = 0; i < 4; ++i) {
        m[i] = -1e30f; l[i] = 0.f;
        op[i][0] = 0ULL; op[i][1] = 0ULL;
    }

    for (int kt = 0; kt < 16; ++kt) {
        const float* kb = qkv + (tok0 + kt * 64) * QKVDIM + DIM + hh * HDIM;
        const float* vb = kb + DIM;

        __syncthreads();
        #pragma unroll
        for (int p = 0; p < 4; ++p) {
            int f = tid + p * 256;
            int row = f >> 4;
            int c4 = (f & 15) << 2;
            float4 kv = *(const float4*)(kb + (size_t)row * QKVDIM + c4);
            kp[(c4 + 0) * 64 + row] = kv.x;
            kp[(c4 + 1) * 64 + row] = kv.y;
            kp[(c4 + 2) * 64 + row] = kv.z;
            kp[(c4 + 3) * 64 + row] = kv.w;
            float4 vv = *(const float4*)(vb + (size_t)row * QKVDIM + c4);
            *(float4*)&vs[row * 64 + c4] = vv;
        }
        __syncthreads();

        unsigned long long sp[4][2];
        #pragma unroll
        for (int i = 0; i < 4; ++i) { sp[i][0] = 0ULL; sp[i][1] = 0ULL; }

        #pragma unroll 4
        for (int d = 0; d < 64; ++d) {
            float4 a = *(const float4*)&qst[d * 64 + ty * 4];
            ulonglong2 b = *(const ulonglong2*)&kp[d * 64 + tx * 4];
            unsigned long long ap0 = pk2(a.x), ap1 = pk2(a.y);
            unsigned long long ap2 = pk2(a.z), ap3 = pk2(a.w);
            fma2(sp[0][0], ap0, b.x); fma2(sp[0][1], ap0, b.y);
            fma2(sp[1][0], ap1, b.x); fma2(sp[1][1], ap1, b.y);
            fma2(sp[2][0], ap2, b.x); fma2(sp[2][1], ap2, b.y);
            fma2(sp[3][0], ap3, b.x); fma2(sp[3][1], ap3, b.y);
        }

        float s[4][4];
        #pragma unroll
        for (int i = 0; i < 4; ++i) {
            float2 t0 = up2(sp[i][0]);
            float2 t1 = up2(sp[i][1]);
            s[i][0] = t0.x * 0.125f;
            s[i][1] = t0.y * 0.125f;
            s[i][2] = t1.x * 0.125f;
            s[i][3] = t1.y * 0.125f;
        }

        float pv4[4][4];
        #pragma unroll
        for (int i = 0; i < 4; ++i) {
            float mt = fmaxf(fmaxf(s[i][0], s[i][1]), fmaxf(s[i][2], s[i][3]));
            #pragma unroll
            for (int off = 8; off > 0; off >>= 1)
                mt = fmaxf(mt, __shfl_xor_sync(0xffffffffu, mt, off));
            float mn = fmaxf(m[i], mt);
            float lsum = 0.f;
            #pragma unroll
            for (int j = 0; j < 4; ++j) {
                pv4[i][j] = __expf(s[i][j] - mn);
                lsum += pv4[i][j];
            }
            #pragma unroll
            for (int off = 8; off > 0; off >>= 1)
                lsum += __shfl_xor_sync(0xffffffffu, lsum, off);
            float alpha = __expf(m[i] - mn);
            l[i] = l[i] * alpha + lsum;
            m[i] = mn;
            unsigned long long ap = pk2(alpha);
            op[i][0] = mul2(op[i][0], ap);
            op[i][1] = mul2(op[i][1], ap);
        }

        __syncthreads();
        #pragma unroll
        for (int i = 0; i < 4; ++i)
            *(float4*)&kp[(ty * 4 + i) * 64 + tx * 4] =
                make_float4(pv4[i][0], pv4[i][1], pv4[i][2], pv4[i][3]);
        __syncthreads();

        #pragma unroll 2
        for (int kk4 = 0; kk4 < 64; kk4 += 4) {
            float4 a4[4];
            #pragma unroll
            for (int i = 0; i < 4; ++i)
                a4[i] = *(const float4*)&kp[(ty * 4 + i) * 64 + kk4];
            #pragma unroll
            for (int u = 0; u < 4; ++u) {
                ulonglong2 b = *(const ulonglong2*)&vs[(kk4 + u) * 64 + tx * 4];
                #pragma unroll
                for (int i = 0; i < 4; ++i) {
                    float av = (u == 0) ? a4[i].x : (u == 1) ? a4[i].y
                             : (u == 2) ? a4[i].z : a4[i].w;
                    unsigned long long ap = pk2(av);
                    fma2(op[i][0], ap, b.x);
                    fma2(op[i][1], ap, b.y);
                }
            }
        }
    }

    const size_t orow0 = tok0 + qt * 64;
    #pragma unroll
    for (int i = 0; i < 4; ++i) {
        float inv = 1.0f / l[i];
        float2 c0 = up2(op[i][0]);
        float2 c1 = up2(op[i][1]);
        float4 r = make_float4(c0.x * inv, c0.y * inv, c1.x * inv, c1.y * inv);
        *(float4*)(out + (orow0 + ty * 4 + i) * DIM + hh * HDIM + tx * 4) = r;
    }
}

// ---------------------------------------------------------------------------
// Fused residual + LayerNorm; optionally emits int8 slices + row scale.
// ---------------------------------------------------------------------------
__device__ __forceinline__ float block_sum256(float x, float* red)
{
    #pragma unroll
    for (int off = 16; off > 0; off >>= 1)
        x += __shfl_down_sync(0xffffffffu, x, off);
    if ((threadIdx.x & 31) == 0) red[threadIdx.x >> 5] = x;
    __syncthreads();
    float r = red[0] + red[1] + red[2] + red[3] +
              red[4] + red[5] + red[6] + red[7];
    __syncthreads();
    return r;
}

__global__ __launch_bounds__(256)
void ln_kernel(const float* __restrict__ h, const float* __restrict__ delta,
               const float* __restrict__ g, const float* __restrict__ b,
               float* __restrict__ out,
               int8_t* __restrict__ p1, int8_t* __restrict__ p2,
               float* __restrict__ sc)
{
    __shared__ float red[8];
    const int row = blockIdx.x;
    const int tid = threadIdx.x;
    const size_t base = (size_t)row * DIM;

    float v[3];
    #pragma unroll
    for (int j = 0; j < 3; ++j) {
        int idx = tid + j * 256;
        float x = h[base + idx];
        if (delta) x += delta[base + idx];
        v[j] = x;
    }
    float mu = block_sum256(v[0] + v[1] + v[2], red) * (1.0f / 768.0f);
    float d0 = v[0] - mu, d1 = v[1] - mu, d2 = v[2] - mu;
    float var = block_sum256(d0 * d0 + d1 * d1 + d2 * d2, red) * (1.0f / 768.0f);
    float rs = rsqrtf(var + 1e-5f);

    float o[3];
    float dd[3] = { d0, d1, d2 };
    float mx = 0.f;
    #pragma unroll
    for (int j = 0; j < 3; ++j) {
        int idx = tid + j * 256;
        o[j] = dd[j] * rs * g[idx] + b[idx];
        out[base + idx] = o[j];
        mx = fmaxf(mx, fabsf(o[j]));
    }
    if (p1) {
        mx = block_max256(mx, red);
        mx = fmaxf(mx, 1e-30f);
        const float inv = 127.f / mx;
        if (tid == 0) sc[row] = mx / 127.f;
        #pragma unroll
        for (int j = 0; j < 3; ++j) {
            int idx = tid + j * 256;
            int8_t q1, q2;
            quant2(o[j], inv, q1, q2);
            p1[base + idx] = q1;
            p2[base + idx] = q2;
        }
    }
}

// ---------------------------------------------------------------------------
// Positional encoding add: h = x + PE, plus int8 slices + row scale.
// ---------------------------------------------------------------------------
__global__ __launch_bounds__(256)
void posenc_kernel(const float* __restrict__ x, float* __restrict__ h,
                   int8_t* __restrict__ p1, int8_t* __restrict__ p2,
                   float* __restrict__ sc)
{
    __shared__ float red[8];
    const int token = blockIdx.x;
    const int s = token & (SEQ - 1);
    float val[3];
    float mx = 0.f;
    #pragma unroll
    for (int j = 0; j < 3; ++j) {
        int d = threadIdx.x + j * 256;
        int i2 = d >> 1;
        float div = expf((float)(2 * i2) * (-9.210340371976184f / 768.0f));
        float ang = (float)s * div;
        float pe = (d & 1) ? cosf(ang) : sinf(ang);
        size_t idx = (size_t)token * DIM + d;
        val[j] = x[idx] + pe;
        h[idx] = val[j];
        mx = fmaxf(mx, fabsf(val[j]));
    }
    mx = block_max256(mx, red);
    mx = fmaxf(mx, 1e-30f);
    const float inv = 127.f / mx;
    if (threadIdx.x == 0) sc[token] = mx / 127.f;
    #pragma unroll
    for (int j = 0; j < 3; ++j) {
        size_t idx = (size_t)token * DIM + threadIdx.x + j * 256;
        int8_t q1, q2;
        quant2(val[j], inv, q1, q2);
        p1[idx] = q1;
        p2[idx] = q2;
    }
}

// ---------------------------------------------------------------------------
// kernel_launch
// ---------------------------------------------------------------------------
extern "C" void kernel_launch(void* const* d_in, const int* in_sizes, int n_in,
                              void* d_out, int out_size)
{
    (void)in_sizes; (void)n_in; (void)out_size;

    const float* x    = (const float*)d_in[0];
    const float* Wqkv = (const float*)d_in[1];
    const float* bqkv = (const float*)d_in[2];
    const float* Wo   = (const float*)d_in[3];
    const float* bo   = (const float*)d_in[4];
    const float* ln1g = (const float*)d_in[5];
    const float* ln1b = (const float*)d_in[6];
    const float* W1   = (const float*)d_in[7];
    const float* b1   = (const float*)d_in[8];
    const float* W2   = (const float*)d_in[9];
    const float* b2   = (const float*)d_in[10];
    const float* ln2g = (const float*)d_in[11];
    const float* ln2b = (const float*)d_in[12];
    const float* lnfg = (const float*)d_in[13];
    const float* lnfb = (const float*)d_in[14];
    float* out = (float*)d_out;

    float *h, *qkvb, *attnb, *tmpb, *ffnb, *wt;
    int8_t *hA1, *hA2, *atA1, *atA2, *ffA1, *ffA2;
    float *sah, *saat, *saff;
    int8_t *Bq1, *Bq2, *Bo1, *Bo2, *B11, *B12, *B21, *B22;
    float *sbq, *sbo, *sb1, *sb2;

    cudaGetSymbolAddress((void**)&h,     g_h);
    cudaGetSymbolAddress((void**)&qkvb,  g_qkv);
    cudaGetSymbolAddress((void**)&attnb, g_attn);
    cudaGetSymbolAddress((void**)&tmpb,  g_tmp);
    cudaGetSymbolAddress((void**)&ffnb,  g_ffn);
    cudaGetSymbolAddress((void**)&wt,    g_wt);
    cudaGetSymbolAddress((void**)&hA1,   g_hA1);
    cudaGetSymbolAddress((void**)&hA2,   g_hA2);
    cudaGetSymbolAddress((void**)&sah,   g_sah);
    cudaGetSymbolAddress((void**)&atA1,  g_atA1);
    cudaGetSymbolAddress((void**)&atA2,  g_atA2);
    cudaGetSymbolAddress((void**)&saat,  g_saat);
    cudaGetSymbolAddress((void**)&ffA1,  g_ffA1);
    cudaGetSymbolAddress((void**)&ffA2,  g_ffA2);
    cudaGetSymbolAddress((void**)&saff,  g_saff);
    cudaGetSymbolAddress((void**)&Bq1,   g_Bq1);
    cudaGetSymbolAddress((void**)&Bq2,   g_Bq2);
    cudaGetSymbolAddress((void**)&sbq,   g_sbq);
    cudaGetSymbolAddress((void**)&Bo1,   g_Bo1);
    cudaGetSymbolAddress((void**)&Bo2,   g_Bo2);
    cudaGetSymbolAddress((void**)&sbo,   g_sbo);
    cudaGetSymbolAddress((void**)&B11,   g_B11);
    cudaGetSymbolAddress((void**)&B12,   g_B12);
    cudaGetSymbolAddress((void**)&sb1,   g_sb1);
    cudaGetSymbolAddress((void**)&B21,   g_B21);
    cudaGetSymbolAddress((void**)&B22,   g_B22);
    cudaGetSymbolAddress((void**)&sb2,   g_sb2);

    cudaFuncSetAttribute(gemm_i8,
                         cudaFuncAttributeMaxDynamicSharedMemorySize,
                         GEMM_SMEM_BYTES);

    // ---- weight prep: transpose to [N,K] then int8 slice rows ----
    dim3 tb(32, 8);
    for (int l = 0; l < NLAYER; ++l) {
        transpose_f32<<<dim3(QKVDIM / 32, DIM / 32), tb>>>(
            Wqkv + (size_t)l * DIM * QKVDIM, wt, DIM, QKVDIM);
        convert_rows<<<QKVDIM, 256>>>(wt, Bq1 + (size_t)l * QKVDIM * DIM,
                                      Bq2 + (size_t)l * QKVDIM * DIM,
                                      sbq + (size_t)l * QKVDIM, DIM);
        transpose_f32<<<dim3(DIM / 32, DIM / 32), tb>>>(
            Wo + (size_t)l * DIM * DIM, wt, DIM, DIM);
        convert_rows<<<DIM, 256>>>(wt, Bo1 + (size_t)l * DIM * DIM,
                                   Bo2 + (size_t)l * DIM * DIM,
                                   sbo + (size_t)l * DIM, DIM);
        transpose_f32<<<dim3(FFDIM / 32, DIM / 32), tb>>>(
            W1 + (size_t)l * DIM * FFDIM, wt, DIM, FFDIM);
        convert_rows<<<FFDIM, 256>>>(wt, B11 + (size_t)l * FFDIM * DIM,
                                     B12 + (size_t)l * FFDIM * DIM,
                                     sb1 + (size_t)l * FFDIM, DIM);
        transpose_f32<<<dim3(DIM / 32, FFDIM / 32), tb>>>(
            W2 + (size_t)l * FFDIM * DIM, wt, FFDIM, DIM);
        convert_rows<<<DIM, 256>>>(wt, B21 + (size_t)l * DIM * FFDIM,
                                   B22 + (size_t)l * DIM * FFDIM,
                                   sb2 + (size_t)l * DIM, FFDIM);
    }

    posenc_kernel<<<T_TOK, 256>>>(x, h, hA1, hA2, sah);

    for (int l = 0; l < NLAYER; ++l) {
        // QKV projection
        gemm_i8<<<dim3(QKVDIM / 64, T_TOK / 128), 256, GEMM_SMEM_BYTES>>>(
            hA1, hA2, sah,
            Bq1 + (size_t)l * QKVDIM * DIM, Bq2 + (size_t)l * QKVDIM * DIM,
            sbq + (size_t)l * QKVDIM,
            bqkv + (size_t)l * QKVDIM, qkvb, T_TOK, QKVDIM, DIM, 0);

        attn_kernel<<<dim3(SEQ / 64, NHEAD, 4), 256>>>(qkvb, attnb);
        convert_rows<<<T_TOK, 256>>>(attnb, atA1, atA2, saat, DIM);

        // output projection
        gemm_i8<<<dim3(DIM / 64, T_TOK / 128), 256, GEMM_SMEM_BYTES>>>(
            atA1, atA2, saat,
            Bo1 + (size_t)l * DIM * DIM, Bo2 + (size_t)l * DIM * DIM,
            sbo + (size_t)l * DIM,
            bo + (size_t)l * DIM, tmpb, T_TOK, DIM, DIM, 0);

        ln_kernel<<<T_TOK, 256>>>(h, tmpb, ln1g + (size_t)l * DIM,
                                  ln1b + (size_t)l * DIM, h, hA1, hA2, sah);

        // FFN up + ReLU
        gemm_i8<<<dim3(FFDIM / 64, T_TOK / 128), 256, GEMM_SMEM_BYTES>>>(
            hA1, hA2, sah,
            B11 + (size_t)l * FFDIM * DIM, B12 + (size_t)l * FFDIM * DIM,
            sb1 + (size_t)l * FFDIM,
            b1 + (size_t)l * FFDIM, ffnb, T_TOK, FFDIM, DIM, 1);
        convert_rows<<<T_TOK, 256>>>(ffnb, ffA1, ffA2, saff, FFDIM);

        // FFN down
        gemm_i8<<<dim3(DIM / 64, T_TOK / 128), 256, GEMM_SMEM_BYTES>>>(
            ffA1, ffA2, saff,
            B21 + (size_t)l * DIM * FFDIM, B22 + (size_t)l * DIM * FFDIM,
            sb2 + (size_t)l * DIM,
            b2 + (size_t)l * DIM, tmpb, T_TOK, DIM, FFDIM, 0);

        ln_kernel<<<T_TOK, 256>>>(h, tmpb, ln2g + (size_t)l * DIM,
                                  ln2b + (size_t)l * DIM, h, hA1, hA2, sah);
    }

    ln_kernel<<<T_TOK, 256>>>(h, nullptr, lnfg, lnfb, out,
                              nullptr, nullptr, nullptr);
}